// round 15
// baseline (speedup 1.0000x reference)
#include <cuda_runtime.h>
#include <cuda_fp16.h>
#include <math.h>

// Problem constants (fixed by the reference)
#define NNODES 100000
#define NEDGES 3200000
#define FIN    11
#define HDIM   32
#define CDIM   16
#define CAP    96      // padded CSR slots per node; deg ~ Poisson(32), P(>=96) ~ e^-41
#define CAP4   24      // CAP in int4 units

#define GE4 3125       // edge blocks, 4 edges/thread (3.2M / 4 / 256, exact)
#define GW  12500      // node-warp blocks for mm1 (100000 / 8, exact)
#define GO  1563       // 8-nodes-per-warp blocks (12500 warps, guarded)
#define GS  6250       // scale blocks: 100000*16 half2 / 256 (exact)

// ---------------- scratch (static __device__ — no allocation allowed) -------
__device__ int    g_cnt[NNODES];                       // in-degree / fill cursor
__device__ float  g_dinv[NNODES];
__device__ __align__(16) int    g_csr[NNODES * CAP];   // padded rows, src only
__device__ __align__(16) __half g_h1[NNODES * HDIM];   // after scale: h1 * dinv
__device__ __align__(16) __half g_h2[NNODES * HDIM];   // h2 * dinv
__device__ __align__(16) __half g_h3[NNODES * CDIM];   // h3 * dinv

// ---------------- fused: CSR fill (blocks [0,GE4)) ∥ mm1 (rest) -------------
__global__ void k_build(const int4* __restrict__ src4, const int4* __restrict__ dst4,
                        const float* __restrict__ x, const float* __restrict__ W1) {
    __shared__ float sW[FIN * HDIM];
    if (blockIdx.x < GE4) {
        int e = blockIdx.x * blockDim.x + threadIdx.x;
        int4 d = __ldcs(&dst4[e]);           // read-once stream: evict-first
        int4 s = __ldcs(&src4[e]);
        g_csr[d.x * CAP + atomicAdd(&g_cnt[d.x], 1)] = s.x;
        g_csr[d.y * CAP + atomicAdd(&g_cnt[d.y], 1)] = s.y;
        g_csr[d.z * CAP + atomicAdd(&g_cnt[d.z], 1)] = s.z;
        g_csr[d.w * CAP + atomicAdd(&g_cnt[d.w], 1)] = s.w;
    } else {
        int t = threadIdx.x;
        for (int i = t; i < FIN * HDIM; i += blockDim.x) sW[i] = W1[i];
        __syncthreads();
        int gw = ((blockIdx.x - GE4) * blockDim.x + t) >> 5;
        int l  = t & 31;
        float xv = (l < FIN) ? x[gw * FIN + l] : 0.0f;
        float acc = 0.0f;
        #pragma unroll
        for (int k = 0; k < FIN; k++)
            acc += __shfl_sync(0xFFFFFFFFu, xv, k) * sW[k * HDIM + l];
        g_h1[gw * HDIM + l] = __float2half(acc);
    }
}

// ---------------- dinv + in-place scale of h1 by dinv (coalesced, half2) ----
__global__ void k_scale() {
    int idx = blockIdx.x * blockDim.x + threadIdx.x;
    int n = idx >> 4;
    float di = rsqrtf((float)g_cnt[n] + 1.0f);
    if ((idx & 15) == 0) g_dinv[n] = di;
    __half2* h = (__half2*)g_h1;
    h[idx] = __hmul2(h[idx], __float2half2_rn(di));
}

#define H2(u) (*(__half2*)&(u))

// ---- gather over one padded CSR row into 4 half2 accs; 16B (uint4) lanes ---
// h = uint4 view of node rows (4 uint4 per 64B row); l in [0,4).
// CSR indices are a read-once stream -> __ldcs keeps them out of L1.
#define GATHER16(h)                                                           \
    const int4* row = (const int4*)&g_csr[n * CAP];                           \
    int deg = g_cnt[n];                                                       \
    int nIt = deg >> 2;                                                       \
    int4 q = __ldcs(&row[0]);                                                 \
    for (int j = 0; j < nIt; j++) {                                           \
        int4 qn = __ldcs(&row[j + 1]);   /* in-bounds: j+1 <= 23 < CAP4 */    \
        uint4 a = h[q.x * 4 + l];                                             \
        uint4 b = h[q.y * 4 + l];                                             \
        uint4 c = h[q.z * 4 + l];                                             \
        uint4 d = h[q.w * 4 + l];                                             \
        acc0 = __hadd2(acc0, __hadd2(__hadd2(H2(a.x), H2(b.x)),               \
                                     __hadd2(H2(c.x), H2(d.x))));             \
        acc1 = __hadd2(acc1, __hadd2(__hadd2(H2(a.y), H2(b.y)),               \
                                     __hadd2(H2(c.y), H2(d.y))));             \
        acc2 = __hadd2(acc2, __hadd2(__hadd2(H2(a.z), H2(b.z)),               \
                                     __hadd2(H2(c.z), H2(d.z))));             \
        acc3 = __hadd2(acc3, __hadd2(__hadd2(H2(a.w), H2(b.w)),               \
                                     __hadd2(H2(c.w), H2(d.w))));             \
        q = qn;                                                               \
    }                                                                         \
    int rem = deg & 3;                   /* q holds the final partial chunk */ \
    if (rem > 0) {                                                            \
        uint4 a = h[q.x * 4 + l];                                             \
        acc0 = __hadd2(acc0, H2(a.x)); acc1 = __hadd2(acc1, H2(a.y));         \
        acc2 = __hadd2(acc2, H2(a.z)); acc3 = __hadd2(acc3, H2(a.w));         \
    }                                                                         \
    if (rem > 1) {                                                            \
        uint4 a = h[q.y * 4 + l];                                             \
        acc0 = __hadd2(acc0, H2(a.x)); acc1 = __hadd2(acc1, H2(a.y));         \
        acc2 = __hadd2(acc2, H2(a.z)); acc3 = __hadd2(acc3, H2(a.w));         \
    }                                                                         \
    if (rem > 2) {                                                            \
        uint4 a = h[q.z * 4 + l];                                             \
        acc0 = __hadd2(acc0, H2(a.x)); acc1 = __hadd2(acc1, H2(a.y));         \
        acc2 = __hadd2(acc2, H2(a.z)); acc3 = __hadd2(acc3, H2(a.w));         \
    }

// ---------------- layer 2: gather(h1') + ReLU + GEMM(W2) -> h2' (fp16) ------
// 8 nodes/warp: sub = lane>>2, lane l in [0,4) holds feats {8l..8l+7}
__global__ void __launch_bounds__(256, 8)
k_l2(const float* __restrict__ b1, const float* __restrict__ W2) {
    __shared__ float4 sW[256];       // sW[k*8+m] = W2[k][4m..4m+3]
    __shared__ float  sb[HDIM];
    int t = threadIdx.x;
    const float4* W2v = (const float4*)W2;
    for (int i = t; i < 256; i += blockDim.x) sW[i] = W2v[i];
    if (t < HDIM) sb[t] = b1[t];
    __syncthreads();

    int gw = (blockIdx.x * blockDim.x + t) >> 5;
    if (gw >= GW) return;                            // warp-uniform exit
    int lane = t & 31;
    int sub  = lane >> 2;
    int l    = lane & 3;
    int n    = gw * 8 + sub;                         // consecutive -> coalesced

    const uint4* h1 = (const uint4*)g_h1;            // [N][4] 16B units
    uint4 sv = h1[n * 4 + l];                        // self (pre-scaled)
    __half2 acc0 = H2(sv.x);
    __half2 acc1 = H2(sv.y);
    __half2 acc2 = H2(sv.z);
    __half2 acc3 = H2(sv.w);
    GATHER16(h1)

    float di = g_dinv[n];
    float2 f0 = __half22float2(acc0);
    float2 f1 = __half22float2(acc1);
    float2 f2 = __half22float2(acc2);
    float2 f3 = __half22float2(acc3);
    float a0 = fmaxf(f0.x * di + sb[8 * l + 0], 0.0f);
    float a1 = fmaxf(f0.y * di + sb[8 * l + 1], 0.0f);
    float a2 = fmaxf(f1.x * di + sb[8 * l + 2], 0.0f);
    float a3 = fmaxf(f1.y * di + sb[8 * l + 3], 0.0f);
    float a4 = fmaxf(f2.x * di + sb[8 * l + 4], 0.0f);
    float a5 = fmaxf(f2.y * di + sb[8 * l + 5], 0.0f);
    float a6 = fmaxf(f3.x * di + sb[8 * l + 6], 0.0f);
    float a7 = fmaxf(f3.y * di + sb[8 * l + 7], 0.0f);

    float hv[8] = {0.f, 0.f, 0.f, 0.f, 0.f, 0.f, 0.f, 0.f};
    #pragma unroll
    for (int g = 0; g < 4; g++) {
        float av[8];
        av[0] = __shfl_sync(0xFFFFFFFFu, a0, g, 4);  // width-4: node's lane g
        av[1] = __shfl_sync(0xFFFFFFFFu, a1, g, 4);
        av[2] = __shfl_sync(0xFFFFFFFFu, a2, g, 4);
        av[3] = __shfl_sync(0xFFFFFFFFu, a3, g, 4);
        av[4] = __shfl_sync(0xFFFFFFFFu, a4, g, 4);
        av[5] = __shfl_sync(0xFFFFFFFFu, a5, g, 4);
        av[6] = __shfl_sync(0xFFFFFFFFu, a6, g, 4);
        av[7] = __shfl_sync(0xFFFFFFFFu, a7, g, 4);
        #pragma unroll
        for (int kk = 0; kk < 8; kk++) {
            int k = g * 8 + kk;
            float4 w0 = sW[k * 8 + 2 * l];
            float4 w1 = sW[k * 8 + 2 * l + 1];
            float v = av[kk];
            hv[0] += v * w0.x; hv[1] += v * w0.y;
            hv[2] += v * w0.z; hv[3] += v * w0.w;
            hv[4] += v * w1.x; hv[5] += v * w1.y;
            hv[6] += v * w1.z; hv[7] += v * w1.w;
        }
    }
    uint4 o;
    *(__half2*)&o.x = __floats2half2_rn(hv[0] * di, hv[1] * di);
    *(__half2*)&o.y = __floats2half2_rn(hv[2] * di, hv[3] * di);
    *(__half2*)&o.z = __floats2half2_rn(hv[4] * di, hv[5] * di);
    *(__half2*)&o.w = __floats2half2_rn(hv[6] * di, hv[7] * di);
    ((uint4*)g_h2)[n * 4 + l] = o;
}

// ---------------- layer 3: gather(h2') + ReLU + GEMM(W3) -> h3' (fp16) ------
// 8 nodes/warp; output C=16: lane l holds classes {4l..4l+3}
__global__ void __launch_bounds__(256, 8)
k_l3(const float* __restrict__ b2, const float* __restrict__ W3) {
    __shared__ float4 sW[128];       // sW[k*4+m] = W3[k][4m..4m+3]
    __shared__ float  sb[HDIM];
    int t = threadIdx.x;
    const float4* W3v = (const float4*)W3;
    for (int i = t; i < 128; i += blockDim.x) sW[i] = W3v[i];
    if (t < HDIM) sb[t] = b2[t];
    __syncthreads();

    int gw = (blockIdx.x * blockDim.x + t) >> 5;
    if (gw >= GW) return;
    int lane = t & 31;
    int sub  = lane >> 2;
    int l    = lane & 3;
    int n    = gw * 8 + sub;

    const uint4* h2 = (const uint4*)g_h2;
    uint4 sv = h2[n * 4 + l];
    __half2 acc0 = H2(sv.x);
    __half2 acc1 = H2(sv.y);
    __half2 acc2 = H2(sv.z);
    __half2 acc3 = H2(sv.w);
    GATHER16(h2)

    float di = g_dinv[n];
    float2 f0 = __half22float2(acc0);
    float2 f1 = __half22float2(acc1);
    float2 f2 = __half22float2(acc2);
    float2 f3 = __half22float2(acc3);
    float a0 = fmaxf(f0.x * di + sb[8 * l + 0], 0.0f);
    float a1 = fmaxf(f0.y * di + sb[8 * l + 1], 0.0f);
    float a2 = fmaxf(f1.x * di + sb[8 * l + 2], 0.0f);
    float a3 = fmaxf(f1.y * di + sb[8 * l + 3], 0.0f);
    float a4 = fmaxf(f2.x * di + sb[8 * l + 4], 0.0f);
    float a5 = fmaxf(f2.y * di + sb[8 * l + 5], 0.0f);
    float a6 = fmaxf(f3.x * di + sb[8 * l + 6], 0.0f);
    float a7 = fmaxf(f3.y * di + sb[8 * l + 7], 0.0f);

    float hv[4] = {0.f, 0.f, 0.f, 0.f};
    #pragma unroll
    for (int g = 0; g < 4; g++) {
        float av[8];
        av[0] = __shfl_sync(0xFFFFFFFFu, a0, g, 4);
        av[1] = __shfl_sync(0xFFFFFFFFu, a1, g, 4);
        av[2] = __shfl_sync(0xFFFFFFFFu, a2, g, 4);
        av[3] = __shfl_sync(0xFFFFFFFFu, a3, g, 4);
        av[4] = __shfl_sync(0xFFFFFFFFu, a4, g, 4);
        av[5] = __shfl_sync(0xFFFFFFFFu, a5, g, 4);
        av[6] = __shfl_sync(0xFFFFFFFFu, a6, g, 4);
        av[7] = __shfl_sync(0xFFFFFFFFu, a7, g, 4);
        #pragma unroll
        for (int kk = 0; kk < 8; kk++) {
            int k = g * 8 + kk;
            float4 w = sW[k * 4 + l];
            float v = av[kk];
            hv[0] += v * w.x; hv[1] += v * w.y;
            hv[2] += v * w.z; hv[3] += v * w.w;
        }
    }
    uint2 o;
    *(__half2*)&o.x = __floats2half2_rn(hv[0] * di, hv[1] * di);
    *(__half2*)&o.y = __floats2half2_rn(hv[2] * di, hv[3] * di);
    ((uint2*)g_h3)[n * 4 + l] = o;                   // node row = 32B = 4 uint2
}

// ---------------- layer 4: gather(h3') + bias + log_softmax -> out ----------
// 8 nodes/warp: sub = lane>>2, lane l in [0,4) holds classes {4l..4l+3}
__global__ void __launch_bounds__(256, 8)
k_l4(const float* __restrict__ b3, float* __restrict__ out) {
    int t    = threadIdx.x;
    int gw   = (blockIdx.x * blockDim.x + t) >> 5;
    if (gw >= GW) return;                            // warp-uniform exit
    int lane = t & 31;
    int sub  = lane >> 2;
    int l    = lane & 3;
    int n    = gw * 8 + sub;

    const uint2* h3 = (const uint2*)g_h3;            // [N][4] 8B units
    uint2 sv = h3[n * 4 + l];
    __half2 acc0 = H2(sv.x);
    __half2 acc1 = H2(sv.y);

    const int4* row = (const int4*)&g_csr[n * CAP];
    int deg = g_cnt[n];
    int nIt = deg >> 2;
    int4 q = __ldcs(&row[0]);
    for (int j = 0; j < nIt; j++) {
        int4 qn = __ldcs(&row[j + 1]);
        uint2 a = h3[q.x * 4 + l];
        uint2 b = h3[q.y * 4 + l];
        uint2 c = h3[q.z * 4 + l];
        uint2 d = h3[q.w * 4 + l];
        acc0 = __hadd2(acc0, __hadd2(__hadd2(H2(a.x), H2(b.x)),
                                     __hadd2(H2(c.x), H2(d.x))));
        acc1 = __hadd2(acc1, __hadd2(__hadd2(H2(a.y), H2(b.y)),
                                     __hadd2(H2(c.y), H2(d.y))));
        q = qn;
    }
    int rem = deg & 3;
    if (rem > 0) {
        uint2 a = h3[q.x * 4 + l];
        acc0 = __hadd2(acc0, H2(a.x)); acc1 = __hadd2(acc1, H2(a.y));
    }
    if (rem > 1) {
        uint2 a = h3[q.y * 4 + l];
        acc0 = __hadd2(acc0, H2(a.x)); acc1 = __hadd2(acc1, H2(a.y));
    }
    if (rem > 2) {
        uint2 a = h3[q.z * 4 + l];
        acc0 = __hadd2(acc0, H2(a.x)); acc1 = __hadd2(acc1, H2(a.y));
    }

    float di = g_dinv[n];
    float2 f0 = __half22float2(acc0);
    float2 f1 = __half22float2(acc1);
    float4 bb = ((const float4*)b3)[l];
    float4 vb;
    vb.x = f0.x * di + bb.x;
    vb.y = f0.y * di + bb.y;
    vb.z = f1.x * di + bb.z;
    vb.w = f1.y * di + bb.w;

    float m = fmaxf(fmaxf(vb.x, vb.y), fmaxf(vb.z, vb.w));
    m = fmaxf(m, __shfl_xor_sync(0xFFFFFFFFu, m, 2));
    m = fmaxf(m, __shfl_xor_sync(0xFFFFFFFFu, m, 1));
    float ss = expf(vb.x - m) + expf(vb.y - m) + expf(vb.z - m) + expf(vb.w - m);
    ss += __shfl_xor_sync(0xFFFFFFFFu, ss, 2);
    ss += __shfl_xor_sync(0xFFFFFFFFu, ss, 1);
    float lse = m + logf(ss);
    ((float4*)out)[n * 4 + l] =
        make_float4(vb.x - lse, vb.y - lse, vb.z - lse, vb.w - lse);
}

// ---------------- launch ----------------------------------------------------
extern "C" void kernel_launch(void* const* d_in, const int* in_sizes, int n_in,
                              void* d_out, int out_size) {
    // metadata order: x, edge_index, W1, b1, W2, b2, W3, b3
    const float* x  = (const float*)d_in[0];
    const int*   ei = (const int*)  d_in[1];   // [2, E]: src first, then dst
    const float* W1 = (const float*)d_in[2];
    const float* b1 = (const float*)d_in[3];
    const float* W2 = (const float*)d_in[4];
    const float* b2 = (const float*)d_in[5];
    const float* W3 = (const float*)d_in[6];
    const float* b3 = (const float*)d_in[7];
    float*       out = (float*)d_out;

    const int4* src4 = (const int4*)ei;
    const int4* dst4 = (const int4*)(ei + NEDGES);

    void* pcnt;
    cudaGetSymbolAddress(&pcnt, g_cnt);

    const int B = 256;
    cudaMemsetAsync(pcnt, 0, NNODES * sizeof(int));
    k_build<<<GE4 + GW, B>>>(src4, dst4, x, W1);
    k_scale<<<GS, B>>>();
    k_l2   <<<GO, B>>>(b1, W2);
    k_l3   <<<GO, B>>>(b2, W3);
    k_l4   <<<GO, B>>>(b3, out);
}

// round 16
// speedup vs baseline: 1.0274x; 1.0274x over previous
#include <cuda_runtime.h>
#include <cuda_fp16.h>
#include <math.h>

// Problem constants (fixed by the reference)
#define NNODES 100000
#define NEDGES 3200000
#define FIN    11
#define HDIM   32
#define CDIM   16
#define CAP    96      // padded CSR slots per node; deg ~ Poisson(32), P(>=96) ~ e^-41
#define CAP4   24      // CAP in int4 units

#define GE4 3125       // edge blocks, 4 edges/thread (3.2M / 4 / 256, exact)
#define GW  12500      // node-warp blocks for mm1 (100000 / 8, exact)
#define GO  1563       // 8-nodes-per-warp blocks (12500 warps, guarded)
#define GS  6250       // scale blocks: 100000*16 half2 / 256 (exact)

// ---------------- scratch (static __device__ — no allocation allowed) -------
__device__ int    g_cnt[NNODES];                       // in-degree / fill cursor
__device__ float  g_dinv[NNODES];
__device__ __align__(16) int    g_csr[NNODES * CAP];   // padded rows, src only
__device__ __align__(16) __half g_h1[NNODES * HDIM];   // after scale: h1 * dinv
__device__ __align__(16) __half g_h2[NNODES * HDIM];   // h2 * dinv
__device__ __align__(16) __half g_h3[NNODES * CDIM];   // h3 * dinv

// ---------------- fused: CSR fill (blocks [0,GE4)) ∥ mm1 (rest) -------------
__global__ void k_build(const int4* __restrict__ src4, const int4* __restrict__ dst4,
                        const float* __restrict__ x, const float* __restrict__ W1) {
    cudaTriggerProgrammaticLaunchCompletion();   // successor may begin prologue
    __shared__ float sW[FIN * HDIM];
    if (blockIdx.x < GE4) {
        int e = blockIdx.x * blockDim.x + threadIdx.x;
        int4 d = dst4[e];
        int4 s = src4[e];
        g_csr[d.x * CAP + atomicAdd(&g_cnt[d.x], 1)] = s.x;
        g_csr[d.y * CAP + atomicAdd(&g_cnt[d.y], 1)] = s.y;
        g_csr[d.z * CAP + atomicAdd(&g_cnt[d.z], 1)] = s.z;
        g_csr[d.w * CAP + atomicAdd(&g_cnt[d.w], 1)] = s.w;
    } else {
        int t = threadIdx.x;
        for (int i = t; i < FIN * HDIM; i += blockDim.x) sW[i] = W1[i];
        __syncthreads();
        int gw = ((blockIdx.x - GE4) * blockDim.x + t) >> 5;
        int l  = t & 31;
        float xv = (l < FIN) ? x[gw * FIN + l] : 0.0f;
        float acc = 0.0f;
        #pragma unroll
        for (int k = 0; k < FIN; k++)
            acc += __shfl_sync(0xFFFFFFFFu, xv, k) * sW[k * HDIM + l];
        g_h1[gw * HDIM + l] = __float2half(acc);
    }
}

// ---------------- dinv + in-place scale of h1 by dinv (coalesced, half2) ----
__global__ void k_scale() {
    cudaTriggerProgrammaticLaunchCompletion();
    cudaGridDependencySynchronize();             // wait for k_build's cnt + h1
    int idx = blockIdx.x * blockDim.x + threadIdx.x;
    int n = idx >> 4;
    float di = rsqrtf((float)g_cnt[n] + 1.0f);
    if ((idx & 15) == 0) g_dinv[n] = di;
    __half2* h = (__half2*)g_h1;
    h[idx] = __hmul2(h[idx], __float2half2_rn(di));
}

#define H2(u) (*(__half2*)&(u))

// ---- gather over one padded CSR row into 4 half2 accs; 16B (uint4) lanes ---
// h = uint4 view of node rows (4 uint4 per 64B row); l in [0,4).
#define GATHER16(h)                                                           \
    const int4* row = (const int4*)&g_csr[n * CAP];                           \
    int deg = g_cnt[n];                                                       \
    int nIt = deg >> 2;                                                       \
    int4 q = row[0];                                                          \
    for (int j = 0; j < nIt; j++) {                                           \
        int4 qn = row[j + 1];            /* in-bounds: j+1 <= 23 < CAP4 */    \
        uint4 a = h[q.x * 4 + l];                                             \
        uint4 b = h[q.y * 4 + l];                                             \
        uint4 c = h[q.z * 4 + l];                                             \
        uint4 d = h[q.w * 4 + l];                                             \
        acc0 = __hadd2(acc0, __hadd2(__hadd2(H2(a.x), H2(b.x)),               \
                                     __hadd2(H2(c.x), H2(d.x))));             \
        acc1 = __hadd2(acc1, __hadd2(__hadd2(H2(a.y), H2(b.y)),               \
                                     __hadd2(H2(c.y), H2(d.y))));             \
        acc2 = __hadd2(acc2, __hadd2(__hadd2(H2(a.z), H2(b.z)),               \
                                     __hadd2(H2(c.z), H2(d.z))));             \
        acc3 = __hadd2(acc3, __hadd2(__hadd2(H2(a.w), H2(b.w)),               \
                                     __hadd2(H2(c.w), H2(d.w))));             \
        q = qn;                                                               \
    }                                                                         \
    int rem = deg & 3;                   /* q holds the final partial chunk */ \
    if (rem > 0) {                                                            \
        uint4 a = h[q.x * 4 + l];                                             \
        acc0 = __hadd2(acc0, H2(a.x)); acc1 = __hadd2(acc1, H2(a.y));         \
        acc2 = __hadd2(acc2, H2(a.z)); acc3 = __hadd2(acc3, H2(a.w));         \
    }                                                                         \
    if (rem > 1) {                                                            \
        uint4 a = h[q.y * 4 + l];                                             \
        acc0 = __hadd2(acc0, H2(a.x)); acc1 = __hadd2(acc1, H2(a.y));         \
        acc2 = __hadd2(acc2, H2(a.z)); acc3 = __hadd2(acc3, H2(a.w));         \
    }                                                                         \
    if (rem > 2) {                                                            \
        uint4 a = h[q.z * 4 + l];                                             \
        acc0 = __hadd2(acc0, H2(a.x)); acc1 = __hadd2(acc1, H2(a.y));         \
        acc2 = __hadd2(acc2, H2(a.z)); acc3 = __hadd2(acc3, H2(a.w));         \
    }

// ---------------- layer 2: gather(h1') + ReLU + GEMM(W2) -> h2' (fp16) ------
// 8 nodes/warp: sub = lane>>2, lane l in [0,4) holds feats {8l..8l+7}
__global__ void __launch_bounds__(256, 8)
k_l2(const float* __restrict__ b1, const float* __restrict__ W2) {
    cudaTriggerProgrammaticLaunchCompletion();
    __shared__ float4 sW[256];       // sW[k*8+m] = W2[k][4m..4m+3]
    __shared__ float  sb[HDIM];
    int t = threadIdx.x;
    // Prologue: weight/bias staging reads only kernel inputs — safe pre-sync.
    const float4* W2v = (const float4*)W2;
    for (int i = t; i < 256; i += blockDim.x) sW[i] = W2v[i];
    if (t < HDIM) sb[t] = b1[t];
    __syncthreads();
    cudaGridDependencySynchronize();             // wait for k_scale's h1'

    int gw = (blockIdx.x * blockDim.x + t) >> 5;
    if (gw >= GW) return;                        // warp-uniform exit
    int lane = t & 31;
    int sub  = lane >> 2;
    int l    = lane & 3;
    int n    = gw * 8 + sub;                     // consecutive -> coalesced

    const uint4* h1 = (const uint4*)g_h1;        // [N][4] 16B units
    uint4 sv = h1[n * 4 + l];                    // self (pre-scaled)
    __half2 acc0 = H2(sv.x);
    __half2 acc1 = H2(sv.y);
    __half2 acc2 = H2(sv.z);
    __half2 acc3 = H2(sv.w);
    GATHER16(h1)

    float di = g_dinv[n];
    float2 f0 = __half22float2(acc0);
    float2 f1 = __half22float2(acc1);
    float2 f2 = __half22float2(acc2);
    float2 f3 = __half22float2(acc3);
    float a0 = fmaxf(f0.x * di + sb[8 * l + 0], 0.0f);
    float a1 = fmaxf(f0.y * di + sb[8 * l + 1], 0.0f);
    float a2 = fmaxf(f1.x * di + sb[8 * l + 2], 0.0f);
    float a3 = fmaxf(f1.y * di + sb[8 * l + 3], 0.0f);
    float a4 = fmaxf(f2.x * di + sb[8 * l + 4], 0.0f);
    float a5 = fmaxf(f2.y * di + sb[8 * l + 5], 0.0f);
    float a6 = fmaxf(f3.x * di + sb[8 * l + 6], 0.0f);
    float a7 = fmaxf(f3.y * di + sb[8 * l + 7], 0.0f);

    float hv[8] = {0.f, 0.f, 0.f, 0.f, 0.f, 0.f, 0.f, 0.f};
    #pragma unroll
    for (int g = 0; g < 4; g++) {
        float av[8];
        av[0] = __shfl_sync(0xFFFFFFFFu, a0, g, 4);  // width-4: node's lane g
        av[1] = __shfl_sync(0xFFFFFFFFu, a1, g, 4);
        av[2] = __shfl_sync(0xFFFFFFFFu, a2, g, 4);
        av[3] = __shfl_sync(0xFFFFFFFFu, a3, g, 4);
        av[4] = __shfl_sync(0xFFFFFFFFu, a4, g, 4);
        av[5] = __shfl_sync(0xFFFFFFFFu, a5, g, 4);
        av[6] = __shfl_sync(0xFFFFFFFFu, a6, g, 4);
        av[7] = __shfl_sync(0xFFFFFFFFu, a7, g, 4);
        #pragma unroll
        for (int kk = 0; kk < 8; kk++) {
            int k = g * 8 + kk;
            float4 w0 = sW[k * 8 + 2 * l];
            float4 w1 = sW[k * 8 + 2 * l + 1];
            float v = av[kk];
            hv[0] += v * w0.x; hv[1] += v * w0.y;
            hv[2] += v * w0.z; hv[3] += v * w0.w;
            hv[4] += v * w1.x; hv[5] += v * w1.y;
            hv[6] += v * w1.z; hv[7] += v * w1.w;
        }
    }
    uint4 o;
    *(__half2*)&o.x = __floats2half2_rn(hv[0] * di, hv[1] * di);
    *(__half2*)&o.y = __floats2half2_rn(hv[2] * di, hv[3] * di);
    *(__half2*)&o.z = __floats2half2_rn(hv[4] * di, hv[5] * di);
    *(__half2*)&o.w = __floats2half2_rn(hv[6] * di, hv[7] * di);
    ((uint4*)g_h2)[n * 4 + l] = o;
}

// ---------------- layer 3: gather(h2') + ReLU + GEMM(W3) -> h3' (fp16) ------
// 8 nodes/warp; output C=16: lane l holds classes {4l..4l+3}
__global__ void __launch_bounds__(256, 8)
k_l3(const float* __restrict__ b2, const float* __restrict__ W3) {
    cudaTriggerProgrammaticLaunchCompletion();
    __shared__ float4 sW[128];       // sW[k*4+m] = W3[k][4m..4m+3]
    __shared__ float  sb[HDIM];
    int t = threadIdx.x;
    const float4* W3v = (const float4*)W3;
    for (int i = t; i < 128; i += blockDim.x) sW[i] = W3v[i];
    if (t < HDIM) sb[t] = b2[t];
    __syncthreads();
    cudaGridDependencySynchronize();             // wait for k_l2's h2'

    int gw = (blockIdx.x * blockDim.x + t) >> 5;
    if (gw >= GW) return;
    int lane = t & 31;
    int sub  = lane >> 2;
    int l    = lane & 3;
    int n    = gw * 8 + sub;

    const uint4* h2 = (const uint4*)g_h2;
    uint4 sv = h2[n * 4 + l];
    __half2 acc0 = H2(sv.x);
    __half2 acc1 = H2(sv.y);
    __half2 acc2 = H2(sv.z);
    __half2 acc3 = H2(sv.w);
    GATHER16(h2)

    float di = g_dinv[n];
    float2 f0 = __half22float2(acc0);
    float2 f1 = __half22float2(acc1);
    float2 f2 = __half22float2(acc2);
    float2 f3 = __half22float2(acc3);
    float a0 = fmaxf(f0.x * di + sb[8 * l + 0], 0.0f);
    float a1 = fmaxf(f0.y * di + sb[8 * l + 1], 0.0f);
    float a2 = fmaxf(f1.x * di + sb[8 * l + 2], 0.0f);
    float a3 = fmaxf(f1.y * di + sb[8 * l + 3], 0.0f);
    float a4 = fmaxf(f2.x * di + sb[8 * l + 4], 0.0f);
    float a5 = fmaxf(f2.y * di + sb[8 * l + 5], 0.0f);
    float a6 = fmaxf(f3.x * di + sb[8 * l + 6], 0.0f);
    float a7 = fmaxf(f3.y * di + sb[8 * l + 7], 0.0f);

    float hv[4] = {0.f, 0.f, 0.f, 0.f};
    #pragma unroll
    for (int g = 0; g < 4; g++) {
        float av[8];
        av[0] = __shfl_sync(0xFFFFFFFFu, a0, g, 4);
        av[1] = __shfl_sync(0xFFFFFFFFu, a1, g, 4);
        av[2] = __shfl_sync(0xFFFFFFFFu, a2, g, 4);
        av[3] = __shfl_sync(0xFFFFFFFFu, a3, g, 4);
        av[4] = __shfl_sync(0xFFFFFFFFu, a4, g, 4);
        av[5] = __shfl_sync(0xFFFFFFFFu, a5, g, 4);
        av[6] = __shfl_sync(0xFFFFFFFFu, a6, g, 4);
        av[7] = __shfl_sync(0xFFFFFFFFu, a7, g, 4);
        #pragma unroll
        for (int kk = 0; kk < 8; kk++) {
            int k = g * 8 + kk;
            float4 w = sW[k * 4 + l];
            float v = av[kk];
            hv[0] += v * w.x; hv[1] += v * w.y;
            hv[2] += v * w.z; hv[3] += v * w.w;
        }
    }
    uint2 o;
    *(__half2*)&o.x = __floats2half2_rn(hv[0] * di, hv[1] * di);
    *(__half2*)&o.y = __floats2half2_rn(hv[2] * di, hv[3] * di);
    ((uint2*)g_h3)[n * 4 + l] = o;               // node row = 32B = 4 uint2
}

// ---------------- layer 4: gather(h3') + bias + log_softmax -> out ----------
// 8 nodes/warp: sub = lane>>2, lane l in [0,4) holds classes {4l..4l+3}
__global__ void __launch_bounds__(256, 8)
k_l4(const float* __restrict__ b3, float* __restrict__ out) {
    cudaTriggerProgrammaticLaunchCompletion();
    cudaGridDependencySynchronize();             // wait for k_l3's h3'
    int t    = threadIdx.x;
    int gw   = (blockIdx.x * blockDim.x + t) >> 5;
    if (gw >= GW) return;                        // warp-uniform exit
    int lane = t & 31;
    int sub  = lane >> 2;
    int l    = lane & 3;
    int n    = gw * 8 + sub;

    const uint2* h3 = (const uint2*)g_h3;        // [N][4] 8B units
    uint2 sv = h3[n * 4 + l];
    __half2 acc0 = H2(sv.x);
    __half2 acc1 = H2(sv.y);

    const int4* row = (const int4*)&g_csr[n * CAP];
    int deg = g_cnt[n];
    int nIt = deg >> 2;
    int4 q = row[0];
    for (int j = 0; j < nIt; j++) {
        int4 qn = row[j + 1];
        uint2 a = h3[q.x * 4 + l];
        uint2 b = h3[q.y * 4 + l];
        uint2 c = h3[q.z * 4 + l];
        uint2 d = h3[q.w * 4 + l];
        acc0 = __hadd2(acc0, __hadd2(__hadd2(H2(a.x), H2(b.x)),
                                     __hadd2(H2(c.x), H2(d.x))));
        acc1 = __hadd2(acc1, __hadd2(__hadd2(H2(a.y), H2(b.y)),
                                     __hadd2(H2(c.y), H2(d.y))));
        q = qn;
    }
    int rem = deg & 3;
    if (rem > 0) {
        uint2 a = h3[q.x * 4 + l];
        acc0 = __hadd2(acc0, H2(a.x)); acc1 = __hadd2(acc1, H2(a.y));
    }
    if (rem > 1) {
        uint2 a = h3[q.y * 4 + l];
        acc0 = __hadd2(acc0, H2(a.x)); acc1 = __hadd2(acc1, H2(a.y));
    }
    if (rem > 2) {
        uint2 a = h3[q.z * 4 + l];
        acc0 = __hadd2(acc0, H2(a.x)); acc1 = __hadd2(acc1, H2(a.y));
    }

    float di = g_dinv[n];
    float2 f0 = __half22float2(acc0);
    float2 f1 = __half22float2(acc1);
    float4 bb = ((const float4*)b3)[l];
    float4 vb;
    vb.x = f0.x * di + bb.x;
    vb.y = f0.y * di + bb.y;
    vb.z = f1.x * di + bb.z;
    vb.w = f1.y * di + bb.w;

    float m = fmaxf(fmaxf(vb.x, vb.y), fmaxf(vb.z, vb.w));
    m = fmaxf(m, __shfl_xor_sync(0xFFFFFFFFu, m, 2));
    m = fmaxf(m, __shfl_xor_sync(0xFFFFFFFFu, m, 1));
    float ss = expf(vb.x - m) + expf(vb.y - m) + expf(vb.z - m) + expf(vb.w - m);
    ss += __shfl_xor_sync(0xFFFFFFFFu, ss, 2);
    ss += __shfl_xor_sync(0xFFFFFFFFu, ss, 1);
    float lse = m + logf(ss);
    ((float4*)out)[n * 4 + l] =
        make_float4(vb.x - lse, vb.y - lse, vb.z - lse, vb.w - lse);
}

// ---------------- launch ----------------------------------------------------
extern "C" void kernel_launch(void* const* d_in, const int* in_sizes, int n_in,
                              void* d_out, int out_size) {
    // metadata order: x, edge_index, W1, b1, W2, b2, W3, b3
    const float* x  = (const float*)d_in[0];
    const int*   ei = (const int*)  d_in[1];   // [2, E]: src first, then dst
    const float* W1 = (const float*)d_in[2];
    const float* b1 = (const float*)d_in[3];
    const float* W2 = (const float*)d_in[4];
    const float* b2 = (const float*)d_in[5];
    const float* W3 = (const float*)d_in[6];
    const float* b3 = (const float*)d_in[7];
    float*       out = (float*)d_out;

    const int4* src4 = (const int4*)ei;
    const int4* dst4 = (const int4*)(ei + NEDGES);

    void* pcnt;
    cudaGetSymbolAddress(&pcnt, g_cnt);

    const int B = 256;
    cudaMemsetAsync(pcnt, 0, NNODES * sizeof(int));
    k_build<<<GE4 + GW, B>>>(src4, dst4, x, W1);

    // PDL launches: successor prologues overlap predecessor tails.
    cudaLaunchAttribute at[1];
    at[0].id = cudaLaunchAttributeProgrammaticStreamSerialization;
    at[0].val.programmaticStreamSerializationAllowed = 1;
    cudaLaunchConfig_t cfg = {};
    cfg.blockDim = dim3(B, 1, 1);
    cfg.attrs = at;
    cfg.numAttrs = 1;
    cfg.stream = 0;

    cfg.gridDim = dim3(GS, 1, 1);
    cudaLaunchKernelEx(&cfg, k_scale);
    cfg.gridDim = dim3(GO, 1, 1);
    cudaLaunchKernelEx(&cfg, k_l2, b1, W2);
    cudaLaunchKernelEx(&cfg, k_l3, b2, W3);
    cudaLaunchKernelEx(&cfg, k_l4, b3, out);
}